// round 12
// baseline (speedup 1.0000x reference)
#include <cuda_runtime.h>
#include <cstdint>

typedef unsigned long long u64;

#define NPTSALL    16384     // BATCH * N_PTS
#define NFACES     10000
#define NPAIRS     5000      // NFACES / 2
#define NSLC       20
#define SLC_PAIRS  250       // NPAIRS / NSLC
#define NSUB       10
#define SUB_PAIRS  25        // SLC_PAIRS / NSUB
#define SSCALE     10.0f

// Scratch (static __device__ arrays; no allocation)
__device__ float4 d_A[NPAIRS];             // (cx0, cx1, cy0, cy1) per center pair
__device__ float4 d_B[NPAIRS];             // (cz0, cz1, c2_0, c2_1) per center pair
__device__ float  d_qval[NSLC * NPTSALL];  // per-slice min score per point
__device__ int    d_qsub[NSLC * NPTSALL];  // winning subtile base pair index
__device__ float2 d_ic[50];                // (ic1, ic2) per Adam step, RUNTIME-built

// ---------------- packed fp32x2 helpers ----------------
__device__ __forceinline__ u64 fma2(u64 a, u64 b, u64 c) {
    u64 d;
    asm("fma.rn.f32x2 %0, %1, %2, %3;" : "=l"(d) : "l"(a), "l"(b), "l"(c));
    return d;
}
__device__ __forceinline__ u64 pk2(float lo, float hi) {
    u64 v; asm("mov.b64 %0, {%1, %2};" : "=l"(v) : "f"(lo), "f"(hi)); return v;
}
__device__ __forceinline__ void upk2(u64 v, float& lo, float& hi) {
    asm("mov.b64 {%0, %1}, %2;" : "=f"(lo), "=f"(hi) : "l"(v));
}

// ---------------- 1) centers + |c|^2 + runtime ic table ----------------
// B1/B2 arrive as RUNTIME kernel parameters, so nvcc cannot constant-fold the
// table: the ops below execute as the same runtime FMUL/FADD/MUFU.RCP/FMUL
// sequence the solve loop used, on the same input bits => bitwise-equal values.
__global__ void pack_centers_kernel(const float* __restrict__ V, const int* __restrict__ F,
                                    float B1, float B2) {
    int f = blockIdx.x * blockDim.x + threadIdx.x;
    if (f == 0) {
        float b1t = 1.0f, b2t = 1.0f;
        for (int t = 0; t < 50; ++t) {
            b1t *= B1; b2t *= B2;
            float ic1 = __fdividef(1.0f, 1.0f - b1t);
            float ic2 = __fdividef(1.0f, 1.0f - b2t);
            d_ic[t] = make_float2(ic1, ic2);
        }
    }
    if (f >= NFACES) return;
    int i0 = F[3*f+0], i1 = F[3*f+1], i2 = F[3*f+2];
    float x = (V[3*i0+0] + V[3*i1+0] + V[3*i2+0]) / 3.0f;
    float y = (V[3*i0+1] + V[3*i1+1] + V[3*i2+1]) / 3.0f;
    float z = (V[3*i0+2] + V[3*i1+2] + V[3*i2+2]) / 3.0f;
    float c2 = x*x + y*y + z*z;
    int p = f >> 1, h = f & 1;
    float* A = (float*)d_A;
    float* B = (float*)d_B;
    A[4*p + h]     = x;
    A[4*p + 2 + h] = y;
    B[4*p + h]     = z;
    B[4*p + 2 + h] = c2;
}

// ---------------- 2a) per-slice min scan, 4 points per thread ----------------
// score_f = |c_f|^2 - 2 q.c_f (|q|^2 dropped: argmin-invariant); exact same fma2
// chain per point as all passing rounds; per-point lo/hi accumulation pattern
// unchanged (fminf over non-NaN is order-free; ties resolved by rescan).
// grid (32, 20) = 640 blocks -> 4.3 blocks/SM, issue-saturated; the 2 LDS.128
// per pair now amortize over 4 query points.
__global__ void __launch_bounds__(128) knnA_kernel(const float* __restrict__ verts) {
    __shared__ ulonglong2 sA[SLC_PAIRS];   // 4 KB
    __shared__ ulonglong2 sB[SLC_PAIRS];   // 4 KB
    int tid = threadIdx.x;
    int slc = blockIdx.y;
    int obase = slc * SLC_PAIRS;

    const ulonglong2* gA = (const ulonglong2*)d_A;
    const ulonglong2* gB = (const ulonglong2*)d_B;
    for (int i = tid; i < SLC_PAIRS; i += 128) { sA[i] = gA[obase + i]; sB[i] = gB[obase + i]; }
    __syncthreads();

    int pt0 = blockIdx.x * 512 + tid;
    u64 qmx[4], qmy[4], qmz[4];
#pragma unroll
    for (int k = 0; k < 4; ++k) {
        int pt = pt0 + k * 128;
        float qx = verts[3*pt+0], qy = verts[3*pt+1], qz = verts[3*pt+2];
        qmx[k] = pk2(-2.0f*qx, -2.0f*qx);
        qmy[k] = pk2(-2.0f*qy, -2.0f*qy);
        qmz[k] = pk2(-2.0f*qz, -2.0f*qz);
    }

    const float INF = __int_as_float(0x7f800000);
    float best[4] = { INF, INF, INF, INF };
    int   sub[4]  = { 0, 0, 0, 0 };

#pragma unroll 1
    for (int s = 0; s < NSUB; ++s) {
        int b = s * SUB_PAIRS;
        float a0[4], a1[4];
#pragma unroll
        for (int k = 0; k < 4; ++k) { a0[k] = INF; a1[k] = INF; }
#pragma unroll 5
        for (int p = 0; p < SUB_PAIRS; ++p) {
            ulonglong2 A = sA[b + p];
            ulonglong2 B = sB[b + p];
#pragma unroll
            for (int k = 0; k < 4; ++k) {
                u64 z  = fma2(B.x, qmz[k], B.y);
                u64 sc = fma2(A.x, qmx[k], fma2(A.y, qmy[k], z));
                float lo, hi; upk2(sc, lo, hi);
                a0[k] = fminf(a0[k], lo);
                a1[k] = fminf(a1[k], hi);
            }
        }
#pragma unroll
        for (int k = 0; k < 4; ++k) {
            float sm = fminf(a0[k], a1[k]);
            if (sm < best[k]) { best[k] = sm; sub[k] = b; }  // strict <: earliest subtile wins
        }
    }
#pragma unroll
    for (int k = 0; k < 4; ++k) {
        int pt = pt0 + k * 128;
        d_qval[slc * NPTSALL + pt] = best[k];
        d_qsub[slc * NPTSALL + pt] = obase + sub[k];
    }
}

// ---------------- 2b + 3) combine/rescan + 4 x 50 Adam solve ----------------
// R8/R11 form; ic1/ic2 now read from the runtime-built (bitwise-identical)
// table instead of being recomputed in-loop. All other ops unchanged bits.
__global__ void __launch_bounds__(128) solve_kernel(
    const float* __restrict__ verts,
    const float* __restrict__ MV,
    const float* __restrict__ MN,
    const int*   __restrict__ MF,
    float* __restrict__ out)
{
    int i = blockIdx.x * 128 + threadIdx.x;

    float qx = verts[3*i+0], qy = verts[3*i+1], qz = verts[3*i+2];

    // ---- combine slice mins (strict <, ascending => first-index ties) ----
    float best = d_qval[i]; int qi = 0;
#pragma unroll
    for (int q = 1; q < NSLC; ++q) {
        float v = d_qval[q * NPTSALL + i];
        if (v < best) { best = v; qi = q; }
    }
    int base = d_qsub[qi * NPTSALL + i];

    // ---- rescan winning 25-pair subtile, first bitwise-equal index ----
    u64 qmx = pk2(-2.0f*qx, -2.0f*qx);
    u64 qmy = pk2(-2.0f*qy, -2.0f*qy);
    u64 qmz = pk2(-2.0f*qz, -2.0f*qz);
    const ulonglong2* gA = (const ulonglong2*)d_A;
    const ulonglong2* gB = (const ulonglong2*)d_B;
    int found = 0x7fffffff;
#pragma unroll 5
    for (int j = 0; j < SUB_PAIRS; ++j) {
        ulonglong2 a = gA[base + j];
        ulonglong2 b = gB[base + j];
        u64 sc = fma2(a.x, qmx, fma2(a.y, qmy, fma2(b.x, qmz, b.y)));
        float lo, hi; upk2(sc, lo, hi);
        if (lo == best) found = min(found, 2*(base + j));
        if (hi == best) found = min(found, 2*(base + j) + 1);
    }
    int fid = (found == 0x7fffffff) ? 0 : found;   // guaranteed found; OOB guard

    // ---- Adam solve (per-op bits identical to R2/R4/R8/R11) ----
    int i0 = MF[3*fid+0], i1 = MF[3*fid+1], i2 = MF[3*fid+2];

    float V0x = MV[3*i0+0], V0y = MV[3*i0+1], V0z = MV[3*i0+2];
    float V1x = MV[3*i1+0], V1y = MV[3*i1+1], V1z = MV[3*i1+2];
    float V2x = MV[3*i2+0], V2y = MV[3*i2+1], V2z = MV[3*i2+2];
    float N0x = MN[3*i0+0], N0y = MN[3*i0+1], N0z = MN[3*i0+2];
    float N1x = MN[3*i1+0], N1y = MN[3*i1+1], N1z = MN[3*i1+2];
    float N2x = MN[3*i2+0], N2y = MN[3*i2+1], N2z = MN[3*i2+2];

    float tgx = SSCALE*qx, tgy = SSCALE*qy, tgz = SSCALE*qz;

    float dVux = V0x - V2x, dVuy = V0y - V2y, dVuz = V0z - V2z;
    float dVvx = V1x - V2x, dVvy = V1y - V2y, dVvz = V1z - V2z;
    float dNux = N0x - N2x, dNuy = N0y - N2y, dNuz = N0z - N2z;
    float dNvx = N1x - N2x, dNvy = N1y - N2y, dNvz = N1z - N2z;

    const float B1 = 0.9f, B2 = 0.999f, LR = 0.01f, EPSA = 1e-8f;
    const float OB1 = 1.0f - 0.9f;
    const float OB2 = 1.0f - 0.999f;
    const float K   = (2.0f / 49152.0f) * SSCALE;  // 2/(3M) * S

    float vwu = 1.0f/3.0f, vwv = 1.0f/3.0f;

#pragma unroll 1
    for (int outer = 0; outer < 4; ++outer) {
        float w0 = 1.0f - vwu - vwv;
        float Px0 = fmaf(vwu, V0x, fmaf(vwv, V1x, w0 * V2x));
        float Py0 = fmaf(vwu, V0y, fmaf(vwv, V1y, w0 * V2y));
        float Pz0 = fmaf(vwu, V0z, fmaf(vwv, V1z, w0 * V2z));
        float ex = Px0 - qx, ey = Py0 - qy, ez = Pz0 - qz;
        float dd = sqrtf(ex*ex + ey*ey + ez*ez);

        float du = 0.0f, dv = 0.0f;
        float mu = 0.0f, mv = 0.0f, md = 0.0f;
        float vu = 0.0f, vvv = 0.0f, vd = 0.0f;

#pragma unroll 1
        for (int t = 0; t < 50; ++t) {
            float2 ic = d_ic[t];
            float ic1 = ic.x;
            float ic2 = ic.y;

            float u = vwu + du, v = vwv + dv;
            float w = 1.0f - u - v;

            float Px = fmaf(u, V0x, fmaf(v, V1x, w * V2x));
            float Py = fmaf(u, V0y, fmaf(v, V1y, w * V2y));
            float Pz = fmaf(u, V0z, fmaf(v, V1z, w * V2z));
            float Nx = fmaf(u, N0x, fmaf(v, N1x, w * N2x));
            float Ny = fmaf(u, N0y, fmaf(v, N1y, w * N2y));
            float Nz = fmaf(u, N0z, fmaf(v, N1z, w * N2z));

            float nn = fmaf(Nx, Nx, fmaf(Ny, Ny, Nz * Nz));
            float l  = sqrtf(nn);
            float rl = __fdividef(1.0f, fmaxf(l, 1e-12f));
            float nx = Nx * rl, ny = Ny * rl, nz = Nz * rl;

            float sd = SSCALE * dd;
            float rx = fmaf(SSCALE, Px, fmaf(sd, nx, -tgx));
            float ry = fmaf(SSCALE, Py, fmaf(sd, ny, -tgy));
            float rz = fmaf(SSCALE, Pz, fmaf(sd, nz, -tgz));

            float rn  = fmaf(rx, nx,   fmaf(ry, ny,   rz * nz));
            float rvu = fmaf(rx, dVux, fmaf(ry, dVuy, rz * dVuz));
            float rvv = fmaf(rx, dVvx, fmaf(ry, dVvy, rz * dVvz));
            float rnu = fmaf(rx, dNux, fmaf(ry, dNuy, rz * dNuz));
            float rnv = fmaf(rx, dNvx, fmaf(ry, dNvy, rz * dNvz));
            float ndu = fmaf(nx, dNux, fmaf(ny, dNuy, nz * dNuz));
            float ndv = fmaf(nx, dNvx, fmaf(ny, dNvy, nz * dNvz));

            float drl = dd * rl;
            float gu = K * fmaf(drl, fmaf(-ndu, rn, rnu), rvu);
            float gv = K * fmaf(drl, fmaf(-ndv, rn, rnv), rvv);
            float gd = K * rn;

            mu = fmaf(B1, mu, OB1 * gu);
            vu = fmaf(B2, vu, OB2 * gu * gu);
            du = fmaf(-LR, __fdividef(mu * ic1, sqrtf(vu * ic2) + EPSA), du);

            mv = fmaf(B1, mv, OB1 * gv);
            vvv = fmaf(B2, vvv, OB2 * gv * gv);
            dv = fmaf(-LR, __fdividef(mv * ic1, sqrtf(vvv * ic2) + EPSA), dv);

            md = fmaf(B1, md, OB1 * gd);
            vd = fmaf(B2, vd, OB2 * gd * gd);
            dd = fmaf(-LR, __fdividef(md * ic1, sqrtf(vd * ic2) + EPSA), dd);
        }
        vwu += du; vwv += dv;
    }

    // Outputs, flattened tuple as float32: fidx | vw | outlier_mask
    out[i] = (float)fid;
    out[NPTSALL + 2*i + 0] = vwu;
    out[NPTSALL + 2*i + 1] = vwv;
    out[3*NPTSALL + i] = 0.0f;
}

extern "C" void kernel_launch(void* const* d_in, const int* in_sizes, int n_in,
                              void* d_out, int out_size) {
    const float* verts  = (const float*)d_in[0];
    const float* mesh_V = (const float*)d_in[1];
    const float* mesh_N = (const float*)d_in[2];
    const int*   mesh_F = (const int*)d_in[3];
    float* out = (float*)d_out;

    pack_centers_kernel<<<(NFACES + 127) / 128, 128>>>(mesh_V, mesh_F, 0.9f, 0.999f);
    dim3 gridA(NPTSALL / 512, NSLC);
    knnA_kernel<<<gridA, 128>>>(verts);
    solve_kernel<<<NPTSALL / 128, 128>>>(verts, mesh_V, mesh_N, mesh_F, out);
}

// round 13
// speedup vs baseline: 1.0152x; 1.0152x over previous
#include <cuda_runtime.h>
#include <cstdint>

typedef unsigned long long u64;

#define NPTSALL    16384     // BATCH * N_PTS
#define NFACES     10000
#define NPAIRS     5000      // NFACES / 2
#define NSLC       20
#define SLC_PAIRS  250       // NPAIRS / NSLC
#define NSUB       10
#define SUB_PAIRS  25        // SLC_PAIRS / NSUB
#define SSCALE     10.0f

// Scratch (static __device__ arrays; no allocation)
__device__ float4 d_A[NPAIRS];             // (cx0, cx1, cy0, cy1) per center pair
__device__ float4 d_B[NPAIRS];             // (cz0, cz1, c2_0, c2_1) per center pair
__device__ float  d_qval[NSLC * NPTSALL];  // per-slice min score per point
__device__ int    d_qsub[NSLC * NPTSALL];  // winning subtile base pair index
__device__ float2 d_ic[50];                // (ic1, ic2) per Adam step, RUNTIME-built

// ---------------- packed fp32x2 helpers ----------------
__device__ __forceinline__ u64 fma2(u64 a, u64 b, u64 c) {
    u64 d;
    asm("fma.rn.f32x2 %0, %1, %2, %3;" : "=l"(d) : "l"(a), "l"(b), "l"(c));
    return d;
}
__device__ __forceinline__ u64 pk2(float lo, float hi) {
    u64 v; asm("mov.b64 %0, {%1, %2};" : "=l"(v) : "f"(lo), "f"(hi)); return v;
}
__device__ __forceinline__ void upk2(u64 v, float& lo, float& hi) {
    asm("mov.b64 {%0, %1}, %2;" : "=f"(lo), "=f"(hi) : "l"(v));
}

// ---------------- 1) centers + |c|^2 + runtime ic table ----------------
// B1/B2 arrive as RUNTIME kernel parameters, so nvcc cannot constant-fold the
// table: the ops execute as the same runtime FMUL/FADD/MUFU sequence the solve
// loop used, on the same input bits => bitwise-equal values (verified R12:
// rel_err unchanged at 8.026817e-4).
__global__ void pack_centers_kernel(const float* __restrict__ V, const int* __restrict__ F,
                                    float B1, float B2) {
    int f = blockIdx.x * blockDim.x + threadIdx.x;
    if (f == 0) {
        float b1t = 1.0f, b2t = 1.0f;
        for (int t = 0; t < 50; ++t) {
            b1t *= B1; b2t *= B2;
            float ic1 = __fdividef(1.0f, 1.0f - b1t);
            float ic2 = __fdividef(1.0f, 1.0f - b2t);
            d_ic[t] = make_float2(ic1, ic2);
        }
    }
    if (f >= NFACES) return;
    int i0 = F[3*f+0], i1 = F[3*f+1], i2 = F[3*f+2];
    float x = (V[3*i0+0] + V[3*i1+0] + V[3*i2+0]) / 3.0f;
    float y = (V[3*i0+1] + V[3*i1+1] + V[3*i2+1]) / 3.0f;
    float z = (V[3*i0+2] + V[3*i1+2] + V[3*i2+2]) / 3.0f;
    float c2 = x*x + y*y + z*z;
    int p = f >> 1, h = f & 1;
    float* A = (float*)d_A;
    float* B = (float*)d_B;
    A[4*p + h]     = x;
    A[4*p + 2 + h] = y;
    B[4*p + h]     = z;
    B[4*p + 2 + h] = c2;
}

// ---------------- 2a) per-slice min scan, 2 points per thread ----------------
// R11 form VERBATIM (validated at 98.6us / rel_err 8.026817e-4).
// grid (64, 20) = 1280 blocks -> 8.65 blocks/SM, tight wave quantization.
__global__ void __launch_bounds__(128) knnA_kernel(const float* __restrict__ verts) {
    __shared__ ulonglong2 sA[SLC_PAIRS];   // 4 KB
    __shared__ ulonglong2 sB[SLC_PAIRS];   // 4 KB
    int tid = threadIdx.x;
    int slc = blockIdx.y;
    int obase = slc * SLC_PAIRS;

    const ulonglong2* gA = (const ulonglong2*)d_A;
    const ulonglong2* gB = (const ulonglong2*)d_B;
    for (int i = tid; i < SLC_PAIRS; i += 128) { sA[i] = gA[obase + i]; sB[i] = gB[obase + i]; }
    __syncthreads();

    int ptA = blockIdx.x * 256 + tid;
    int ptB = ptA + 128;
    float qxA = verts[3*ptA+0], qyA = verts[3*ptA+1], qzA = verts[3*ptA+2];
    float qxB = verts[3*ptB+0], qyB = verts[3*ptB+1], qzB = verts[3*ptB+2];
    u64 qmxA = pk2(-2.0f*qxA, -2.0f*qxA);
    u64 qmyA = pk2(-2.0f*qyA, -2.0f*qyA);
    u64 qmzA = pk2(-2.0f*qzA, -2.0f*qzA);
    u64 qmxB = pk2(-2.0f*qxB, -2.0f*qxB);
    u64 qmyB = pk2(-2.0f*qyB, -2.0f*qyB);
    u64 qmzB = pk2(-2.0f*qzB, -2.0f*qzB);

    const float INF = __int_as_float(0x7f800000);
    float bestA = INF, bestB = INF;
    int subA = 0, subB = 0;

#pragma unroll 1
    for (int s = 0; s < NSUB; ++s) {
        int b = s * SUB_PAIRS;
        float a0 = INF, a1 = INF, b0 = INF, b1 = INF;
#pragma unroll 5
        for (int p = 0; p < SUB_PAIRS; ++p) {
            ulonglong2 A = sA[b + p];
            ulonglong2 B = sB[b + p];
            u64 zA = fma2(B.x, qmzA, B.y);
            u64 zB = fma2(B.x, qmzB, B.y);
            u64 scA = fma2(A.x, qmxA, fma2(A.y, qmyA, zA));
            u64 scB = fma2(A.x, qmxB, fma2(A.y, qmyB, zB));
            float lA, hA, lB, hB;
            upk2(scA, lA, hA); upk2(scB, lB, hB);
            a0 = fminf(a0, lA); a1 = fminf(a1, hA);
            b0 = fminf(b0, lB); b1 = fminf(b1, hB);
        }
        float smA = fminf(a0, a1);
        float smB = fminf(b0, b1);
        if (smA < bestA) { bestA = smA; subA = b; }   // strict <: earliest subtile wins
        if (smB < bestB) { bestB = smB; subB = b; }
    }
    d_qval[slc * NPTSALL + ptA] = bestA;
    d_qsub[slc * NPTSALL + ptA] = obase + subA;
    d_qval[slc * NPTSALL + ptB] = bestB;
    d_qsub[slc * NPTSALL + ptB] = obase + subB;
}

// ---------------- 2b + 3) combine/rescan + 4 x 50 Adam solve ----------------
// R11 form with ic1/ic2 read from the runtime-built bitwise-identical table
// (single-variable test vs R11). All other ops unchanged bits.
__global__ void __launch_bounds__(128) solve_kernel(
    const float* __restrict__ verts,
    const float* __restrict__ MV,
    const float* __restrict__ MN,
    const int*   __restrict__ MF,
    float* __restrict__ out)
{
    int i = blockIdx.x * 128 + threadIdx.x;

    float qx = verts[3*i+0], qy = verts[3*i+1], qz = verts[3*i+2];

    // ---- combine slice mins (strict <, ascending => first-index ties) ----
    float best = d_qval[i]; int qi = 0;
#pragma unroll
    for (int q = 1; q < NSLC; ++q) {
        float v = d_qval[q * NPTSALL + i];
        if (v < best) { best = v; qi = q; }
    }
    int base = d_qsub[qi * NPTSALL + i];

    // ---- rescan winning 25-pair subtile, first bitwise-equal index ----
    u64 qmx = pk2(-2.0f*qx, -2.0f*qx);
    u64 qmy = pk2(-2.0f*qy, -2.0f*qy);
    u64 qmz = pk2(-2.0f*qz, -2.0f*qz);
    const ulonglong2* gA = (const ulonglong2*)d_A;
    const ulonglong2* gB = (const ulonglong2*)d_B;
    int found = 0x7fffffff;
#pragma unroll 5
    for (int j = 0; j < SUB_PAIRS; ++j) {
        ulonglong2 a = gA[base + j];
        ulonglong2 b = gB[base + j];
        u64 sc = fma2(a.x, qmx, fma2(a.y, qmy, fma2(b.x, qmz, b.y)));
        float lo, hi; upk2(sc, lo, hi);
        if (lo == best) found = min(found, 2*(base + j));
        if (hi == best) found = min(found, 2*(base + j) + 1);
    }
    int fid = (found == 0x7fffffff) ? 0 : found;   // guaranteed found; OOB guard

    // ---- Adam solve (per-op bits identical to R2/R4/R8/R11) ----
    int i0 = MF[3*fid+0], i1 = MF[3*fid+1], i2 = MF[3*fid+2];

    float V0x = MV[3*i0+0], V0y = MV[3*i0+1], V0z = MV[3*i0+2];
    float V1x = MV[3*i1+0], V1y = MV[3*i1+1], V1z = MV[3*i1+2];
    float V2x = MV[3*i2+0], V2y = MV[3*i2+1], V2z = MV[3*i2+2];
    float N0x = MN[3*i0+0], N0y = MN[3*i0+1], N0z = MN[3*i0+2];
    float N1x = MN[3*i1+0], N1y = MN[3*i1+1], N1z = MN[3*i1+2];
    float N2x = MN[3*i2+0], N2y = MN[3*i2+1], N2z = MN[3*i2+2];

    float tgx = SSCALE*qx, tgy = SSCALE*qy, tgz = SSCALE*qz;

    float dVux = V0x - V2x, dVuy = V0y - V2y, dVuz = V0z - V2z;
    float dVvx = V1x - V2x, dVvy = V1y - V2y, dVvz = V1z - V2z;
    float dNux = N0x - N2x, dNuy = N0y - N2y, dNuz = N0z - N2z;
    float dNvx = N1x - N2x, dNvy = N1y - N2y, dNvz = N1z - N2z;

    const float B1 = 0.9f, B2 = 0.999f, LR = 0.01f, EPSA = 1e-8f;
    const float OB1 = 1.0f - 0.9f;
    const float OB2 = 1.0f - 0.999f;
    const float K   = (2.0f / 49152.0f) * SSCALE;  // 2/(3M) * S

    float vwu = 1.0f/3.0f, vwv = 1.0f/3.0f;

#pragma unroll 1
    for (int outer = 0; outer < 4; ++outer) {
        float w0 = 1.0f - vwu - vwv;
        float Px0 = fmaf(vwu, V0x, fmaf(vwv, V1x, w0 * V2x));
        float Py0 = fmaf(vwu, V0y, fmaf(vwv, V1y, w0 * V2y));
        float Pz0 = fmaf(vwu, V0z, fmaf(vwv, V1z, w0 * V2z));
        float ex = Px0 - qx, ey = Py0 - qy, ez = Pz0 - qz;
        float dd = sqrtf(ex*ex + ey*ey + ez*ez);

        float du = 0.0f, dv = 0.0f;
        float mu = 0.0f, mv = 0.0f, md = 0.0f;
        float vu = 0.0f, vvv = 0.0f, vd = 0.0f;

#pragma unroll 1
        for (int t = 0; t < 50; ++t) {
            float2 ic = d_ic[t];
            float ic1 = ic.x;
            float ic2 = ic.y;

            float u = vwu + du, v = vwv + dv;
            float w = 1.0f - u - v;

            float Px = fmaf(u, V0x, fmaf(v, V1x, w * V2x));
            float Py = fmaf(u, V0y, fmaf(v, V1y, w * V2y));
            float Pz = fmaf(u, V0z, fmaf(v, V1z, w * V2z));
            float Nx = fmaf(u, N0x, fmaf(v, N1x, w * N2x));
            float Ny = fmaf(u, N0y, fmaf(v, N1y, w * N2y));
            float Nz = fmaf(u, N0z, fmaf(v, N1z, w * N2z));

            float nn = fmaf(Nx, Nx, fmaf(Ny, Ny, Nz * Nz));
            float l  = sqrtf(nn);
            float rl = __fdividef(1.0f, fmaxf(l, 1e-12f));
            float nx = Nx * rl, ny = Ny * rl, nz = Nz * rl;

            float sd = SSCALE * dd;
            float rx = fmaf(SSCALE, Px, fmaf(sd, nx, -tgx));
            float ry = fmaf(SSCALE, Py, fmaf(sd, ny, -tgy));
            float rz = fmaf(SSCALE, Pz, fmaf(sd, nz, -tgz));

            float rn  = fmaf(rx, nx,   fmaf(ry, ny,   rz * nz));
            float rvu = fmaf(rx, dVux, fmaf(ry, dVuy, rz * dVuz));
            float rvv = fmaf(rx, dVvx, fmaf(ry, dVvy, rz * dVvz));
            float rnu = fmaf(rx, dNux, fmaf(ry, dNuy, rz * dNuz));
            float rnv = fmaf(rx, dNvx, fmaf(ry, dNvy, rz * dNvz));
            float ndu = fmaf(nx, dNux, fmaf(ny, dNuy, nz * dNuz));
            float ndv = fmaf(nx, dNvx, fmaf(ny, dNvy, nz * dNvz));

            float drl = dd * rl;
            float gu = K * fmaf(drl, fmaf(-ndu, rn, rnu), rvu);
            float gv = K * fmaf(drl, fmaf(-ndv, rn, rnv), rvv);
            float gd = K * rn;

            mu = fmaf(B1, mu, OB1 * gu);
            vu = fmaf(B2, vu, OB2 * gu * gu);
            du = fmaf(-LR, __fdividef(mu * ic1, sqrtf(vu * ic2) + EPSA), du);

            mv = fmaf(B1, mv, OB1 * gv);
            vvv = fmaf(B2, vvv, OB2 * gv * gv);
            dv = fmaf(-LR, __fdividef(mv * ic1, sqrtf(vvv * ic2) + EPSA), dv);

            md = fmaf(B1, md, OB1 * gd);
            vd = fmaf(B2, vd, OB2 * gd * gd);
            dd = fmaf(-LR, __fdividef(md * ic1, sqrtf(vd * ic2) + EPSA), dd);
        }
        vwu += du; vwv += dv;
    }

    // Outputs, flattened tuple as float32: fidx | vw | outlier_mask
    out[i] = (float)fid;
    out[NPTSALL + 2*i + 0] = vwu;
    out[NPTSALL + 2*i + 1] = vwv;
    out[3*NPTSALL + i] = 0.0f;
}

extern "C" void kernel_launch(void* const* d_in, const int* in_sizes, int n_in,
                              void* d_out, int out_size) {
    const float* verts  = (const float*)d_in[0];
    const float* mesh_V = (const float*)d_in[1];
    const float* mesh_N = (const float*)d_in[2];
    const int*   mesh_F = (const int*)d_in[3];
    float* out = (float*)d_out;

    pack_centers_kernel<<<(NFACES + 127) / 128, 128>>>(mesh_V, mesh_F, 0.9f, 0.999f);
    dim3 gridA(NPTSALL / 256, NSLC);
    knnA_kernel<<<gridA, 128>>>(verts);
    solve_kernel<<<NPTSALL / 128, 128>>>(verts, mesh_V, mesh_N, mesh_F, out);
}

// round 14
// speedup vs baseline: 1.0389x; 1.0233x over previous
#include <cuda_runtime.h>
#include <cstdint>

typedef unsigned long long u64;

#define NPTSALL    16384     // BATCH * N_PTS
#define NFACES     10000
#define NPAIRS     5000      // NFACES / 2
#define NSLC       20
#define SLC_PAIRS  250       // NPAIRS / NSLC
#define NSUB       10
#define SUB_PAIRS  25        // SLC_PAIRS / NSUB
#define SSCALE     10.0f

// Scratch (static __device__ arrays; no allocation)
__device__ float4 d_A[NPAIRS];             // (cx0, cx1, cy0, cy1) per center pair
__device__ float4 d_B[NPAIRS];             // (cz0, cz1, c2_0, c2_1) per center pair
__device__ float  d_qval[NSLC * NPTSALL];  // per-slice min score per point
__device__ int    d_qsub[NSLC * NPTSALL];  // winning subtile base pair index

// ---------------- packed fp32x2 helpers ----------------
__device__ __forceinline__ u64 fma2(u64 a, u64 b, u64 c) {
    u64 d;
    asm("fma.rn.f32x2 %0, %1, %2, %3;" : "=l"(d) : "l"(a), "l"(b), "l"(c));
    return d;
}
__device__ __forceinline__ u64 pk2(float lo, float hi) {
    u64 v; asm("mov.b64 %0, {%1, %2};" : "=l"(v) : "f"(lo), "f"(hi)); return v;
}
__device__ __forceinline__ void upk2(u64 v, float& lo, float& hi) {
    asm("mov.b64 {%0, %1}, %2;" : "=f"(lo), "=f"(hi) : "l"(v));
}

// ---------------- 1) centers + |c|^2 (one thread per face) ----------------
__global__ void pack_centers_kernel(const float* __restrict__ V, const int* __restrict__ F) {
    int f = blockIdx.x * blockDim.x + threadIdx.x;
    if (f >= NFACES) return;
    int i0 = F[3*f+0], i1 = F[3*f+1], i2 = F[3*f+2];
    float x = (V[3*i0+0] + V[3*i1+0] + V[3*i2+0]) / 3.0f;
    float y = (V[3*i0+1] + V[3*i1+1] + V[3*i2+1]) / 3.0f;
    float z = (V[3*i0+2] + V[3*i1+2] + V[3*i2+2]) / 3.0f;
    float c2 = x*x + y*y + z*z;
    int p = f >> 1, h = f & 1;
    float* A = (float*)d_A;
    float* B = (float*)d_B;
    A[4*p + h]     = x;
    A[4*p + 2 + h] = y;
    B[4*p + h]     = z;
    B[4*p + 2 + h] = c2;
}

// ---------------- 2a) per-slice min scan, 2 points per thread ----------------
// R11 form VERBATIM (validated at 98.6us / rel_err 8.026817e-4).
// grid (64, 20) = 1280 blocks -> 8.65 blocks/SM, tight wave quantization.
__global__ void __launch_bounds__(128) knnA_kernel(const float* __restrict__ verts) {
    __shared__ ulonglong2 sA[SLC_PAIRS];   // 4 KB
    __shared__ ulonglong2 sB[SLC_PAIRS];   // 4 KB
    int tid = threadIdx.x;
    int slc = blockIdx.y;
    int obase = slc * SLC_PAIRS;

    const ulonglong2* gA = (const ulonglong2*)d_A;
    const ulonglong2* gB = (const ulonglong2*)d_B;
    for (int i = tid; i < SLC_PAIRS; i += 128) { sA[i] = gA[obase + i]; sB[i] = gB[obase + i]; }
    __syncthreads();

    int ptA = blockIdx.x * 256 + tid;
    int ptB = ptA + 128;
    float qxA = verts[3*ptA+0], qyA = verts[3*ptA+1], qzA = verts[3*ptA+2];
    float qxB = verts[3*ptB+0], qyB = verts[3*ptB+1], qzB = verts[3*ptB+2];
    u64 qmxA = pk2(-2.0f*qxA, -2.0f*qxA);
    u64 qmyA = pk2(-2.0f*qyA, -2.0f*qyA);
    u64 qmzA = pk2(-2.0f*qzA, -2.0f*qzA);
    u64 qmxB = pk2(-2.0f*qxB, -2.0f*qxB);
    u64 qmyB = pk2(-2.0f*qyB, -2.0f*qyB);
    u64 qmzB = pk2(-2.0f*qzB, -2.0f*qzB);

    const float INF = __int_as_float(0x7f800000);
    float bestA = INF, bestB = INF;
    int subA = 0, subB = 0;

#pragma unroll 1
    for (int s = 0; s < NSUB; ++s) {
        int b = s * SUB_PAIRS;
        float a0 = INF, a1 = INF, b0 = INF, b1 = INF;
#pragma unroll 5
        for (int p = 0; p < SUB_PAIRS; ++p) {
            ulonglong2 A = sA[b + p];
            ulonglong2 B = sB[b + p];
            u64 zA = fma2(B.x, qmzA, B.y);
            u64 zB = fma2(B.x, qmzB, B.y);
            u64 scA = fma2(A.x, qmxA, fma2(A.y, qmyA, zA));
            u64 scB = fma2(A.x, qmxB, fma2(A.y, qmyB, zB));
            float lA, hA, lB, hB;
            upk2(scA, lA, hA); upk2(scB, lB, hB);
            a0 = fminf(a0, lA); a1 = fminf(a1, hA);
            b0 = fminf(b0, lB); b1 = fminf(b1, hB);
        }
        float smA = fminf(a0, a1);
        float smB = fminf(b0, b1);
        if (smA < bestA) { bestA = smA; subA = b; }   // strict <: earliest subtile wins
        if (smB < bestB) { bestB = smB; subB = b; }
    }
    d_qval[slc * NPTSALL + ptA] = bestA;
    d_qsub[slc * NPTSALL + ptA] = obase + subA;
    d_qval[slc * NPTSALL + ptB] = bestB;
    d_qsub[slc * NPTSALL + ptB] = obase + subB;
}

// ---------------- 2b + 3) combine/rescan + 4 x 50 Adam solve ----------------
// R11 numerics VERBATIM (inline ic — the table LDG regressed in R13).
// Scheduling-only changes: inner loop unrolled 2x (same op sequence, wider
// window so iteration t's independent u/v/d Adam tails overlap t+1's head),
// and minBlocksPerMultiprocessor=1 to give ptxas full register freedom.
__global__ void __launch_bounds__(128, 1) solve_kernel(
    const float* __restrict__ verts,
    const float* __restrict__ MV,
    const float* __restrict__ MN,
    const int*   __restrict__ MF,
    float* __restrict__ out)
{
    int i = blockIdx.x * 128 + threadIdx.x;

    float qx = verts[3*i+0], qy = verts[3*i+1], qz = verts[3*i+2];

    // ---- combine slice mins (strict <, ascending => first-index ties) ----
    float best = d_qval[i]; int qi = 0;
#pragma unroll
    for (int q = 1; q < NSLC; ++q) {
        float v = d_qval[q * NPTSALL + i];
        if (v < best) { best = v; qi = q; }
    }
    int base = d_qsub[qi * NPTSALL + i];

    // ---- rescan winning 25-pair subtile, first bitwise-equal index ----
    u64 qmx = pk2(-2.0f*qx, -2.0f*qx);
    u64 qmy = pk2(-2.0f*qy, -2.0f*qy);
    u64 qmz = pk2(-2.0f*qz, -2.0f*qz);
    const ulonglong2* gA = (const ulonglong2*)d_A;
    const ulonglong2* gB = (const ulonglong2*)d_B;
    int found = 0x7fffffff;
#pragma unroll 5
    for (int j = 0; j < SUB_PAIRS; ++j) {
        ulonglong2 a = gA[base + j];
        ulonglong2 b = gB[base + j];
        u64 sc = fma2(a.x, qmx, fma2(a.y, qmy, fma2(b.x, qmz, b.y)));
        float lo, hi; upk2(sc, lo, hi);
        if (lo == best) found = min(found, 2*(base + j));
        if (hi == best) found = min(found, 2*(base + j) + 1);
    }
    int fid = (found == 0x7fffffff) ? 0 : found;   // guaranteed found; OOB guard

    // ---- Adam solve (numerics identical to R2/R4/R8/R11) ----
    int i0 = MF[3*fid+0], i1 = MF[3*fid+1], i2 = MF[3*fid+2];

    float V0x = MV[3*i0+0], V0y = MV[3*i0+1], V0z = MV[3*i0+2];
    float V1x = MV[3*i1+0], V1y = MV[3*i1+1], V1z = MV[3*i1+2];
    float V2x = MV[3*i2+0], V2y = MV[3*i2+1], V2z = MV[3*i2+2];
    float N0x = MN[3*i0+0], N0y = MN[3*i0+1], N0z = MN[3*i0+2];
    float N1x = MN[3*i1+0], N1y = MN[3*i1+1], N1z = MN[3*i1+2];
    float N2x = MN[3*i2+0], N2y = MN[3*i2+1], N2z = MN[3*i2+2];

    float tgx = SSCALE*qx, tgy = SSCALE*qy, tgz = SSCALE*qz;

    float dVux = V0x - V2x, dVuy = V0y - V2y, dVuz = V0z - V2z;
    float dVvx = V1x - V2x, dVvy = V1y - V2y, dVvz = V1z - V2z;
    float dNux = N0x - N2x, dNuy = N0y - N2y, dNuz = N0z - N2z;
    float dNvx = N1x - N2x, dNvy = N1y - N2y, dNvz = N1z - N2z;

    const float B1 = 0.9f, B2 = 0.999f, LR = 0.01f, EPSA = 1e-8f;
    const float OB1 = 1.0f - 0.9f;
    const float OB2 = 1.0f - 0.999f;
    const float K   = (2.0f / 49152.0f) * SSCALE;  // 2/(3M) * S

    float vwu = 1.0f/3.0f, vwv = 1.0f/3.0f;

#pragma unroll 1
    for (int outer = 0; outer < 4; ++outer) {
        float w0 = 1.0f - vwu - vwv;
        float Px0 = fmaf(vwu, V0x, fmaf(vwv, V1x, w0 * V2x));
        float Py0 = fmaf(vwu, V0y, fmaf(vwv, V1y, w0 * V2y));
        float Pz0 = fmaf(vwu, V0z, fmaf(vwv, V1z, w0 * V2z));
        float ex = Px0 - qx, ey = Py0 - qy, ez = Pz0 - qz;
        float dd = sqrtf(ex*ex + ey*ey + ez*ez);

        float du = 0.0f, dv = 0.0f;
        float mu = 0.0f, mv = 0.0f, md = 0.0f;
        float vu = 0.0f, vvv = 0.0f, vd = 0.0f;
        float b1t = 1.0f, b2t = 1.0f;

#pragma unroll 2
        for (int t = 0; t < 50; ++t) {
            b1t *= B1; b2t *= B2;
            float u = vwu + du, v = vwv + dv;
            float w = 1.0f - u - v;

            float Px = fmaf(u, V0x, fmaf(v, V1x, w * V2x));
            float Py = fmaf(u, V0y, fmaf(v, V1y, w * V2y));
            float Pz = fmaf(u, V0z, fmaf(v, V1z, w * V2z));
            float Nx = fmaf(u, N0x, fmaf(v, N1x, w * N2x));
            float Ny = fmaf(u, N0y, fmaf(v, N1y, w * N2y));
            float Nz = fmaf(u, N0z, fmaf(v, N1z, w * N2z));

            float nn = fmaf(Nx, Nx, fmaf(Ny, Ny, Nz * Nz));
            float l  = sqrtf(nn);
            float rl = __fdividef(1.0f, fmaxf(l, 1e-12f));
            float nx = Nx * rl, ny = Ny * rl, nz = Nz * rl;

            float sd = SSCALE * dd;
            float rx = fmaf(SSCALE, Px, fmaf(sd, nx, -tgx));
            float ry = fmaf(SSCALE, Py, fmaf(sd, ny, -tgy));
            float rz = fmaf(SSCALE, Pz, fmaf(sd, nz, -tgz));

            float rn  = fmaf(rx, nx,   fmaf(ry, ny,   rz * nz));
            float rvu = fmaf(rx, dVux, fmaf(ry, dVuy, rz * dVuz));
            float rvv = fmaf(rx, dVvx, fmaf(ry, dVvy, rz * dVvz));
            float rnu = fmaf(rx, dNux, fmaf(ry, dNuy, rz * dNuz));
            float rnv = fmaf(rx, dNvx, fmaf(ry, dNvy, rz * dNvz));
            float ndu = fmaf(nx, dNux, fmaf(ny, dNuy, nz * dNuz));
            float ndv = fmaf(nx, dNvx, fmaf(ny, dNvy, nz * dNvz));

            float drl = dd * rl;
            float gu = K * fmaf(drl, fmaf(-ndu, rn, rnu), rvu);
            float gv = K * fmaf(drl, fmaf(-ndv, rn, rnv), rvv);
            float gd = K * rn;

            float ic1 = __fdividef(1.0f, 1.0f - b1t);
            float ic2 = __fdividef(1.0f, 1.0f - b2t);

            mu = fmaf(B1, mu, OB1 * gu);
            vu = fmaf(B2, vu, OB2 * gu * gu);
            du = fmaf(-LR, __fdividef(mu * ic1, sqrtf(vu * ic2) + EPSA), du);

            mv = fmaf(B1, mv, OB1 * gv);
            vvv = fmaf(B2, vvv, OB2 * gv * gv);
            dv = fmaf(-LR, __fdividef(mv * ic1, sqrtf(vvv * ic2) + EPSA), dv);

            md = fmaf(B1, md, OB1 * gd);
            vd = fmaf(B2, vd, OB2 * gd * gd);
            dd = fmaf(-LR, __fdividef(md * ic1, sqrtf(vd * ic2) + EPSA), dd);
        }
        vwu += du; vwv += dv;
    }

    // Outputs, flattened tuple as float32: fidx | vw | outlier_mask
    out[i] = (float)fid;
    out[NPTSALL + 2*i + 0] = vwu;
    out[NPTSALL + 2*i + 1] = vwv;
    out[3*NPTSALL + i] = 0.0f;
}

extern "C" void kernel_launch(void* const* d_in, const int* in_sizes, int n_in,
                              void* d_out, int out_size) {
    const float* verts  = (const float*)d_in[0];
    const float* mesh_V = (const float*)d_in[1];
    const float* mesh_N = (const float*)d_in[2];
    const int*   mesh_F = (const int*)d_in[3];
    float* out = (float*)d_out;

    pack_centers_kernel<<<(NFACES + 127) / 128, 128>>>(mesh_V, mesh_F);
    dim3 gridA(NPTSALL / 256, NSLC);
    knnA_kernel<<<gridA, 128>>>(verts);
    solve_kernel<<<NPTSALL / 128, 128>>>(verts, mesh_V, mesh_N, mesh_F, out);
}

// round 15
// speedup vs baseline: 1.0581x; 1.0185x over previous
#include <cuda_runtime.h>
#include <cstdint>

typedef unsigned long long u64;

#define NPTSALL    16384     // BATCH * N_PTS
#define NFACES     10000
#define NPAIRS     5000      // NFACES / 2
#define NSLC       40
#define SLC_PAIRS  125       // NPAIRS / NSLC
#define NSUB       5
#define SUB_PAIRS  25        // SLC_PAIRS / NSUB
#define SSCALE     10.0f

// Scratch (static __device__ arrays; no allocation)
__device__ float4 d_A[NPAIRS];             // (cx0, cx1, cy0, cy1) per center pair
__device__ float4 d_B[NPAIRS];             // (cz0, cz1, c2_0, c2_1) per center pair
__device__ float  d_qval[NSLC * NPTSALL];  // per-slice min score per point
__device__ int    d_qsub[NSLC * NPTSALL];  // winning subtile base pair index

// ---------------- packed fp32x2 helpers ----------------
__device__ __forceinline__ u64 fma2(u64 a, u64 b, u64 c) {
    u64 d;
    asm("fma.rn.f32x2 %0, %1, %2, %3;" : "=l"(d) : "l"(a), "l"(b), "l"(c));
    return d;
}
__device__ __forceinline__ u64 pk2(float lo, float hi) {
    u64 v; asm("mov.b64 %0, {%1, %2};" : "=l"(v) : "f"(lo), "f"(hi)); return v;
}
__device__ __forceinline__ void upk2(u64 v, float& lo, float& hi) {
    asm("mov.b64 {%0, %1}, %2;" : "=f"(lo), "=f"(hi) : "l"(v));
}

// ---------------- 1) centers + |c|^2 (one thread per face) ----------------
__global__ void pack_centers_kernel(const float* __restrict__ V, const int* __restrict__ F) {
    int f = blockIdx.x * blockDim.x + threadIdx.x;
    if (f >= NFACES) return;
    int i0 = F[3*f+0], i1 = F[3*f+1], i2 = F[3*f+2];
    float x = (V[3*i0+0] + V[3*i1+0] + V[3*i2+0]) / 3.0f;
    float y = (V[3*i0+1] + V[3*i1+1] + V[3*i2+1]) / 3.0f;
    float z = (V[3*i0+2] + V[3*i1+2] + V[3*i2+2]) / 3.0f;
    float c2 = x*x + y*y + z*z;
    int p = f >> 1, h = f & 1;
    float* A = (float*)d_A;
    float* B = (float*)d_B;
    A[4*p + h]     = x;
    A[4*p + 2 + h] = y;
    B[4*p + h]     = z;
    B[4*p + 2 + h] = c2;
}

// ---------------- 2a) per-slice min scan, 4 points per thread ----------------
// score_f = |c_f|^2 - 2 q.c_f (|q|^2 dropped: argmin-invariant); exact same fma2
// chain + per-point lo/hi fminf accumulation as all passing rounds (4-pt pattern
// validated bit-exact in R12). grid (32, 40) = 1280 blocks -> 8.65 blocks/SM
// (the R11-validated wave quantization) with the 4-pt LDS amortization
// (5.5 vs 6.0 inst per point-pair). Min VALUE per 25-pair subtile; strict <
// ascending => first-index ties.
__global__ void __launch_bounds__(128) knnA_kernel(const float* __restrict__ verts) {
    __shared__ ulonglong2 sA[SLC_PAIRS];   // 2 KB
    __shared__ ulonglong2 sB[SLC_PAIRS];   // 2 KB
    int tid = threadIdx.x;
    int slc = blockIdx.y;
    int obase = slc * SLC_PAIRS;

    const ulonglong2* gA = (const ulonglong2*)d_A;
    const ulonglong2* gB = (const ulonglong2*)d_B;
    if (tid < SLC_PAIRS) { sA[tid] = gA[obase + tid]; sB[tid] = gB[obase + tid]; }
    __syncthreads();

    int pt0 = blockIdx.x * 512 + tid;
    u64 qmx[4], qmy[4], qmz[4];
#pragma unroll
    for (int k = 0; k < 4; ++k) {
        int pt = pt0 + k * 128;
        float qx = verts[3*pt+0], qy = verts[3*pt+1], qz = verts[3*pt+2];
        qmx[k] = pk2(-2.0f*qx, -2.0f*qx);
        qmy[k] = pk2(-2.0f*qy, -2.0f*qy);
        qmz[k] = pk2(-2.0f*qz, -2.0f*qz);
    }

    const float INF = __int_as_float(0x7f800000);
    float best[4] = { INF, INF, INF, INF };
    int   sub[4]  = { 0, 0, 0, 0 };

#pragma unroll 1
    for (int s = 0; s < NSUB; ++s) {
        int b = s * SUB_PAIRS;
        float a0[4], a1[4];
#pragma unroll
        for (int k = 0; k < 4; ++k) { a0[k] = INF; a1[k] = INF; }
#pragma unroll 5
        for (int p = 0; p < SUB_PAIRS; ++p) {
            ulonglong2 A = sA[b + p];
            ulonglong2 B = sB[b + p];
#pragma unroll
            for (int k = 0; k < 4; ++k) {
                u64 z  = fma2(B.x, qmz[k], B.y);
                u64 sc = fma2(A.x, qmx[k], fma2(A.y, qmy[k], z));
                float lo, hi; upk2(sc, lo, hi);
                a0[k] = fminf(a0[k], lo);
                a1[k] = fminf(a1[k], hi);
            }
        }
#pragma unroll
        for (int k = 0; k < 4; ++k) {
            float sm = fminf(a0[k], a1[k]);
            if (sm < best[k]) { best[k] = sm; sub[k] = b; }  // strict <: earliest subtile wins
        }
    }
#pragma unroll
    for (int k = 0; k < 4; ++k) {
        int pt = pt0 + k * 128;
        d_qval[slc * NPTSALL + pt] = best[k];
        d_qsub[slc * NPTSALL + pt] = obase + sub[k];
    }
}

// ---------------- 2b + 3) combine/rescan + 4 x 50 Adam solve ----------------
// R11 form VERBATIM (validated at 98.6us / rel_err 8.026817e-4); only the
// combine loop count changed 20 -> 40 (strict <, ascending => first-index ties).
__global__ void __launch_bounds__(128) solve_kernel(
    const float* __restrict__ verts,
    const float* __restrict__ MV,
    const float* __restrict__ MN,
    const int*   __restrict__ MF,
    float* __restrict__ out)
{
    int i = blockIdx.x * 128 + threadIdx.x;

    float qx = verts[3*i+0], qy = verts[3*i+1], qz = verts[3*i+2];

    // ---- combine slice mins (strict <, ascending => first-index ties) ----
    float best = d_qval[i]; int qi = 0;
#pragma unroll
    for (int q = 1; q < NSLC; ++q) {
        float v = d_qval[q * NPTSALL + i];
        if (v < best) { best = v; qi = q; }
    }
    int base = d_qsub[qi * NPTSALL + i];

    // ---- rescan winning 25-pair subtile, first bitwise-equal index ----
    u64 qmx = pk2(-2.0f*qx, -2.0f*qx);
    u64 qmy = pk2(-2.0f*qy, -2.0f*qy);
    u64 qmz = pk2(-2.0f*qz, -2.0f*qz);
    const ulonglong2* gA = (const ulonglong2*)d_A;
    const ulonglong2* gB = (const ulonglong2*)d_B;
    int found = 0x7fffffff;
#pragma unroll 5
    for (int j = 0; j < SUB_PAIRS; ++j) {
        ulonglong2 a = gA[base + j];
        ulonglong2 b = gB[base + j];
        u64 sc = fma2(a.x, qmx, fma2(a.y, qmy, fma2(b.x, qmz, b.y)));
        float lo, hi; upk2(sc, lo, hi);
        if (lo == best) found = min(found, 2*(base + j));
        if (hi == best) found = min(found, 2*(base + j) + 1);
    }
    int fid = (found == 0x7fffffff) ? 0 : found;   // guaranteed found; OOB guard

    // ---- Adam solve (numerics identical to R2/R4/R8/R11) ----
    int i0 = MF[3*fid+0], i1 = MF[3*fid+1], i2 = MF[3*fid+2];

    float V0x = MV[3*i0+0], V0y = MV[3*i0+1], V0z = MV[3*i0+2];
    float V1x = MV[3*i1+0], V1y = MV[3*i1+1], V1z = MV[3*i1+2];
    float V2x = MV[3*i2+0], V2y = MV[3*i2+1], V2z = MV[3*i2+2];
    float N0x = MN[3*i0+0], N0y = MN[3*i0+1], N0z = MN[3*i0+2];
    float N1x = MN[3*i1+0], N1y = MN[3*i1+1], N1z = MN[3*i1+2];
    float N2x = MN[3*i2+0], N2y = MN[3*i2+1], N2z = MN[3*i2+2];

    float tgx = SSCALE*qx, tgy = SSCALE*qy, tgz = SSCALE*qz;

    float dVux = V0x - V2x, dVuy = V0y - V2y, dVuz = V0z - V2z;
    float dVvx = V1x - V2x, dVvy = V1y - V2y, dVvz = V1z - V2z;
    float dNux = N0x - N2x, dNuy = N0y - N2y, dNuz = N0z - N2z;
    float dNvx = N1x - N2x, dNvy = N1y - N2y, dNvz = N1z - N2z;

    const float B1 = 0.9f, B2 = 0.999f, LR = 0.01f, EPSA = 1e-8f;
    const float OB1 = 1.0f - 0.9f;
    const float OB2 = 1.0f - 0.999f;
    const float K   = (2.0f / 49152.0f) * SSCALE;  // 2/(3M) * S

    float vwu = 1.0f/3.0f, vwv = 1.0f/3.0f;

#pragma unroll 1
    for (int outer = 0; outer < 4; ++outer) {
        float w0 = 1.0f - vwu - vwv;
        float Px0 = fmaf(vwu, V0x, fmaf(vwv, V1x, w0 * V2x));
        float Py0 = fmaf(vwu, V0y, fmaf(vwv, V1y, w0 * V2y));
        float Pz0 = fmaf(vwu, V0z, fmaf(vwv, V1z, w0 * V2z));
        float ex = Px0 - qx, ey = Py0 - qy, ez = Pz0 - qz;
        float dd = sqrtf(ex*ex + ey*ey + ez*ez);

        float du = 0.0f, dv = 0.0f;
        float mu = 0.0f, mv = 0.0f, md = 0.0f;
        float vu = 0.0f, vvv = 0.0f, vd = 0.0f;
        float b1t = 1.0f, b2t = 1.0f;

#pragma unroll 1
        for (int t = 0; t < 50; ++t) {
            b1t *= B1; b2t *= B2;
            float u = vwu + du, v = vwv + dv;
            float w = 1.0f - u - v;

            float Px = fmaf(u, V0x, fmaf(v, V1x, w * V2x));
            float Py = fmaf(u, V0y, fmaf(v, V1y, w * V2y));
            float Pz = fmaf(u, V0z, fmaf(v, V1z, w * V2z));
            float Nx = fmaf(u, N0x, fmaf(v, N1x, w * N2x));
            float Ny = fmaf(u, N0y, fmaf(v, N1y, w * N2y));
            float Nz = fmaf(u, N0z, fmaf(v, N1z, w * N2z));

            float nn = fmaf(Nx, Nx, fmaf(Ny, Ny, Nz * Nz));
            float l  = sqrtf(nn);
            float rl = __fdividef(1.0f, fmaxf(l, 1e-12f));
            float nx = Nx * rl, ny = Ny * rl, nz = Nz * rl;

            float sd = SSCALE * dd;
            float rx = fmaf(SSCALE, Px, fmaf(sd, nx, -tgx));
            float ry = fmaf(SSCALE, Py, fmaf(sd, ny, -tgy));
            float rz = fmaf(SSCALE, Pz, fmaf(sd, nz, -tgz));

            float rn  = fmaf(rx, nx,   fmaf(ry, ny,   rz * nz));
            float rvu = fmaf(rx, dVux, fmaf(ry, dVuy, rz * dVuz));
            float rvv = fmaf(rx, dVvx, fmaf(ry, dVvy, rz * dVvz));
            float rnu = fmaf(rx, dNux, fmaf(ry, dNuy, rz * dNuz));
            float rnv = fmaf(rx, dNvx, fmaf(ry, dNvy, rz * dNvz));
            float ndu = fmaf(nx, dNux, fmaf(ny, dNuy, nz * dNuz));
            float ndv = fmaf(nx, dNvx, fmaf(ny, dNvy, nz * dNvz));

            float drl = dd * rl;
            float gu = K * fmaf(drl, fmaf(-ndu, rn, rnu), rvu);
            float gv = K * fmaf(drl, fmaf(-ndv, rn, rnv), rvv);
            float gd = K * rn;

            float ic1 = __fdividef(1.0f, 1.0f - b1t);
            float ic2 = __fdividef(1.0f, 1.0f - b2t);

            mu = fmaf(B1, mu, OB1 * gu);
            vu = fmaf(B2, vu, OB2 * gu * gu);
            du = fmaf(-LR, __fdividef(mu * ic1, sqrtf(vu * ic2) + EPSA), du);

            mv = fmaf(B1, mv, OB1 * gv);
            vvv = fmaf(B2, vvv, OB2 * gv * gv);
            dv = fmaf(-LR, __fdividef(mv * ic1, sqrtf(vvv * ic2) + EPSA), dv);

            md = fmaf(B1, md, OB1 * gd);
            vd = fmaf(B2, vd, OB2 * gd * gd);
            dd = fmaf(-LR, __fdividef(md * ic1, sqrtf(vd * ic2) + EPSA), dd);
        }
        vwu += du; vwv += dv;
    }

    // Outputs, flattened tuple as float32: fidx | vw | outlier_mask
    out[i] = (float)fid;
    out[NPTSALL + 2*i + 0] = vwu;
    out[NPTSALL + 2*i + 1] = vwv;
    out[3*NPTSALL + i] = 0.0f;
}

extern "C" void kernel_launch(void* const* d_in, const int* in_sizes, int n_in,
                              void* d_out, int out_size) {
    const float* verts  = (const float*)d_in[0];
    const float* mesh_V = (const float*)d_in[1];
    const float* mesh_N = (const float*)d_in[2];
    const int*   mesh_F = (const int*)d_in[3];
    float* out = (float*)d_out;

    pack_centers_kernel<<<(NFACES + 127) / 128, 128>>>(mesh_V, mesh_F);
    dim3 gridA(NPTSALL / 512, NSLC);
    knnA_kernel<<<gridA, 128>>>(verts);
    solve_kernel<<<NPTSALL / 128, 128>>>(verts, mesh_V, mesh_N, mesh_F, out);
}